// round 14
// baseline (speedup 1.0000x reference)
#include <cuda_runtime.h>
#include <cstdint>
#include <cstddef>

#define Bq 4
#define Sq 2048
#define Dq 1024
#define Hq 16
#define DKq 64
#define Mrows (Bq*Sq)
#define NTILES 32          // key tiles per (b,h)
#define NCH 32             // K chunks per GEMM (K=1024 / 32)
#define LNEG -1e30f

// Scratch (allocation-free rule: __device__ globals)
__device__ uint4 g_qp[(size_t)64*16*2048];         // packed Q tiles (QA layout)
__device__ uint4 g_kp[(size_t)64*NTILES*1024];     // packed K fragments (paired n8)
__device__ uint4 g_vp[(size_t)64*NTILES*1024];     // packed V fragments (paired n8)
__device__ uint4 g_xp[(size_t)Mrows*Dq/4];          // packed x   (A layout)
__device__ uint4 g_ap[(size_t)Mrows*Dq/4];          // packed attn out (A layout)
__device__ uint4 g_wq[(size_t)Dq*Dq/4];             // packed weights (B layout)
__device__ uint4 g_wk[(size_t)Dq*Dq/4];
__device__ uint4 g_wv[(size_t)Dq*Dq/4];
__device__ uint4 g_wo[(size_t)Dq*Dq/4];

__device__ __forceinline__ uint32_t f2tf(float f) {
    uint32_t u;
    asm("cvt.rna.tf32.f32 %0, %1;" : "=r"(u) : "f"(f));
    return u;
}
__device__ __forceinline__ float ex2(float x) {
    float r;
    asm("ex2.approx.f32 %0, %1;" : "=f"(r) : "f"(x));
    return r;
}
__device__ __forceinline__ void mma_tf32(float* c, uint4 a, uint32_t b0, uint32_t b1) {
    asm volatile("mma.sync.aligned.m16n8k8.row.col.f32.tf32.tf32.f32 "
        "{%0,%1,%2,%3}, {%4,%5,%6,%7}, {%8,%9}, {%0,%1,%2,%3};"
        : "+f"(c[0]), "+f"(c[1]), "+f"(c[2]), "+f"(c[3])
        : "r"(a.x), "r"(a.y), "r"(a.z), "r"(a.w), "r"(b0), "r"(b1));
}
__device__ __forceinline__ void cp16(uint32_t sa, const void* g) {
    asm volatile("cp.async.cg.shared.global [%0], [%1], 16;" :: "r"(sa), "l"(g));
}

// ---------------------------------------------------------------------------
// Pack a float matrix [R x 1024] into A-layout fragment tiles (TF32).
// ---------------------------------------------------------------------------
__global__ void __launch_bounds__(256) pack_a(const float* __restrict__ A,
                                              uint32_t* __restrict__ out)
{
    const int rb = blockIdx.x, ch = blockIdx.y, tid = threadIdx.x;
    const int rbase = tid >> 3, kc = (tid & 7) << 2;
    const int ks = (tid & 7) >> 1, hi = tid & 1;
    uint32_t* ot = out + ((size_t)rb * NCH + ch) * 4096;
    const float* Ab = A + ((size_t)rb * 128) * Dq + ch * 32;
    #pragma unroll
    for (int i = 0; i < 4; ++i) {
        int r = rbase + 32*i;
        float4 f4 = *reinterpret_cast<const float4*>(Ab + (size_t)r * Dq + kc);
        const float* f = &f4.x;
        int mt = r >> 4, rr = r & 15;
        int w = (rr >> 3) + (hi << 1);
        int base = (mt*4 + ks) * 32;
        int l0 = (rr & 7) << 2;
        #pragma unroll
        for (int j = 0; j < 4; ++j)
            ot[(base + ((l0 + j) ^ (ks << 1))) * 4 + w] = f2tf(f[j]);
    }
}

// ---------------------------------------------------------------------------
// Pack the 4 weight matrices into B-layout fragment tiles.
// ---------------------------------------------------------------------------
__global__ void __launch_bounds__(256) pack_w(const float* __restrict__ w0,
                                              const float* __restrict__ w1,
                                              const float* __restrict__ w2,
                                              const float* __restrict__ w3,
                                              uint32_t* __restrict__ o0,
                                              uint32_t* __restrict__ o1,
                                              uint32_t* __restrict__ o2,
                                              uint32_t* __restrict__ o3)
{
    const float* W = (blockIdx.z == 0) ? w0 : (blockIdx.z == 1) ? w1
                    : (blockIdx.z == 2) ? w2 : w3;
    uint32_t* O = (blockIdx.z == 0) ? o0 : (blockIdx.z == 1) ? o1
                 : (blockIdx.z == 2) ? o2 : o3;
    const int nb = blockIdx.x, ch = blockIdx.y, tid = threadIdx.x;
    const int rbase = tid >> 3, kc = (tid & 7) << 2;
    const int ks = (tid & 7) >> 1, hi = tid & 1;
    uint32_t* ot = O + ((size_t)nb * NCH + ch) * 4096;
    const float* Wb = W + ((size_t)nb * 128) * Dq + ch * 32;
    #pragma unroll
    for (int i = 0; i < 4; ++i) {
        int n = rbase + 32*i;
        float4 f4 = *reinterpret_cast<const float4*>(Wb + (size_t)n * Dq + kc);
        const float* f = &f4.x;
        int nt = n >> 3, gg = n & 7;
        int w = ((nt & 1) << 1) + hi;
        int base = ((nt >> 1)*4 + ks) * 32;
        int l0 = gg << 2;
        #pragma unroll
        for (int j = 0; j < 4; ++j)
            ot[(base + ((l0 + j) ^ (ks << 1))) * 4 + w] = f2tf(f[j]);
    }
}

// ---------------------------------------------------------------------------
// Fused QKV TF32 GEMM on pre-packed operands. grid (8, 64, 3).
// z=0 -> Q in attn QA fragment layout (scaled by 0.125*log2e);
// z=1 -> paired kp; z=2 -> paired vp.
// ---------------------------------------------------------------------------
extern __shared__ uint32_t gsm[];
__global__ void __launch_bounds__(256, 2) gemm_qkv(const uint4* __restrict__ Ap,
                                                   const uint4* __restrict__ Bq_,
                                                   const uint4* __restrict__ Bk_,
                                                   const uint4* __restrict__ Bv_,
                                                   uint32_t* __restrict__ qp32,
                                                   uint32_t* __restrict__ kp32,
                                                   uint32_t* __restrict__ vp32)
{
    const int tid = threadIdx.x;
    const int lane = tid & 31, wid = tid >> 5;
    const int wm = wid >> 1, wn = wid & 1;
    const int g = lane >> 2, t = lane & 3;
    const int z = blockIdx.z;
    const uint4* Bp = (z == 0) ? Bq_ : (z == 1) ? Bk_ : Bv_;
    const size_t tA0 = (size_t)blockIdx.y * NCH;
    const size_t tB0 = (size_t)blockIdx.x * NCH;
    const uint32_t sbase = (uint32_t)__cvta_generic_to_shared(gsm);

    float acc[2][8][4];
    #pragma unroll
    for (int mt = 0; mt < 2; ++mt)
        #pragma unroll
        for (int j = 0; j < 8; ++j)
            #pragma unroll
            for (int e = 0; e < 4; ++e) acc[mt][j][e] = 0.f;

    auto prefetch = [&](int ch, int s) {
        const uint4* ga = Ap + (tA0 + ch) * 1024 + tid;
        const uint4* gb = Bp + (tB0 + ch) * 1024 + tid;
        uint32_t sA = sbase + s * 32768;
        uint32_t sB = sA + 16384;
        #pragma unroll
        for (int i = 0; i < 4; ++i)
            cp16(sA + (tid + (i << 8)) * 16, ga + (i << 8));
        #pragma unroll
        for (int i = 0; i < 4; ++i)
            cp16(sB + (tid + (i << 8)) * 16, gb + (i << 8));
    };

    prefetch(0, 0);
    asm volatile("cp.async.commit_group;");
    prefetch(1, 1);
    asm volatile("cp.async.commit_group;");

    for (int ch = 0; ch < NCH; ++ch) {
        const int s = ch % 3;
        asm volatile("cp.async.wait_group 1;");
        __syncthreads();
        if (ch + 2 < NCH) prefetch(ch + 2, (ch + 2) % 3);
        asm volatile("cp.async.commit_group;");

        const uint32_t* As = gsm + s * 8192;
        const uint32_t* Bs = As + 4096;
        #pragma unroll
        for (int ks = 0; ks < 4; ++ks) {
            uint4 af[2], bf[4];
            const int sl = lane ^ (ks << 1);
            #pragma unroll
            for (int mt = 0; mt < 2; ++mt)
                af[mt] = *reinterpret_cast<const uint4*>(
                    &As[(((wm*2 + mt)*4 + ks)*32 + sl) * 4]);
            #pragma unroll
            for (int p = 0; p < 4; ++p)
                bf[p] = *reinterpret_cast<const uint4*>(
                    &Bs[(((wn*4 + p)*4 + ks)*32 + sl) * 4]);
            #pragma unroll
            for (int mt = 0; mt < 2; ++mt)
                #pragma unroll
                for (int p = 0; p < 4; ++p) {
                    mma_tf32(acc[mt][2*p],   af[mt], bf[p].x, bf[p].y);
                    mma_tf32(acc[mt][2*p+1], af[mt], bf[p].z, bf[p].w);
                }
        }
    }

    const int bm = blockIdx.y * 128, bn = blockIdx.x * 128;

    // All epilogues stage via smem; pipeline is dead after this point.
    asm volatile("cp.async.wait_group 0;");
    __syncthreads();

    if (z == 0) {
        // Q: stage attn QA fragment layout (scaled), 2 head-quadrants x 32KB
        const float qsc = 0.125f * 1.44269504f;
        #pragma unroll
        for (int mt = 0; mt < 2; ++mt)
            #pragma unroll
            for (int j = 0; j < 8; ++j)
                #pragma unroll
                for (int e = 0; e < 4; ++e) {
                    int rloc = wm*32 + mt*16 + g + ((e >> 1) << 3);   // 0..127
                    int nloc = wn*64 + j*8 + 2*t + (e & 1);           // 0..127
                    int ch2 = nloc >> 6, dkl = nloc & 63;
                    int sl = rloc >> 4, ri = rloc & 15;
                    int gg = ri & 7, half = ri >> 3;
                    int kk = dkl >> 3, cc = dkl & 7;
                    int tt = cc & 3, hi4 = cc >> 2;
                    int idx = (sl*256 + gg*32 + 4*(kk ^ gg) + tt)*4 + half + 2*hi4;
                    gsm[ch2*8192 + idx] = f2tf(acc[mt][j][e] * qsc);
                }
        __syncthreads();
        const int b = bm >> 11, qt = (bm & 2047) >> 7, h0 = bn >> 6;
        #pragma unroll
        for (int ch2 = 0; ch2 < 2; ++ch2) {
            int bh = b*16 + h0 + ch2;
            uint4* dst = reinterpret_cast<uint4*>(qp32) + ((size_t)bh*16 + qt) * 2048;
            const uint4* src = reinterpret_cast<const uint4*>(gsm) + ch2 * 2048;
            #pragma unroll
            for (int i = 0; i < 8; ++i)
                dst[tid + (i << 8)] = src[tid + (i << 8)];
        }
        return;
    }

    // K/V: stage paired-fragment layout into smem, then coalesced copy
    #pragma unroll
    for (int mt = 0; mt < 2; ++mt)
        #pragma unroll
        for (int j = 0; j < 8; ++j)
            #pragma unroll
            for (int e = 0; e < 4; ++e) {
                int rloc = wm*32 + mt*16 + g + ((e >> 1) << 3);   // 0..127
                int nloc = wn*64 + j*8 + 2*t + (e & 1);           // 0..127
                int rh = rloc >> 6, ch2 = nloc >> 6;
                int keyl = rloc & 63, dkl = nloc & 63;
                int idx;
                if (z == 1) {
                    int gq = keyl & 7, n8k = keyl >> 3;
                    int qk = n8k >> 1, half = n8k & 1;
                    int kk2 = dkl >> 3, dc = dkl & 7;
                    idx = ((qk*8 + gq)*32 + 4*(kk2 ^ gq) + (dc & 3))*4 + half*2 + (dc >> 2);
                } else {
                    int gq = dkl & 7, n8v = dkl >> 3;
                    int qv = n8v >> 1, half = n8v & 1;
                    int kk3 = keyl >> 3, kc2 = keyl & 7;
                    idx = ((qv*8 + gq)*32 + 4*(kk3 ^ gq) + (kc2 & 3))*4 + half*2 + (kc2 >> 2);
                }
                gsm[(rh*2 + ch2)*4096 + idx] = f2tf(acc[mt][j][e]);
            }
    __syncthreads();

    uint32_t* dstb = (z == 1) ? kp32 : vp32;
    const int b = bm >> 11, jt0 = (bm & 2047) >> 6, h0 = bn >> 6;
    #pragma unroll
    for (int qd = 0; qd < 4; ++qd) {
        int rh = qd >> 1, ch2 = qd & 1;
        int bh = b*16 + h0 + ch2;
        int jt = jt0 + rh;
        uint4* dst = reinterpret_cast<uint4*>(dstb) + ((size_t)bh*NTILES + jt) * 1024;
        const uint4* src = reinterpret_cast<const uint4*>(gsm) + qd * 1024;
        #pragma unroll
        for (int i = 0; i < 4; ++i)
            dst[tid + (i << 8)] = src[tid + (i << 8)];
    }
}

// ---------------------------------------------------------------------------
// TF32 GEMM on pre-packed operands (final O-projection), float epilogue.
// ---------------------------------------------------------------------------
__global__ void __launch_bounds__(256, 2) gemm_packed(const uint4* __restrict__ Ap,
                                                      const uint4* __restrict__ Bp,
                                                      float* __restrict__ C)
{
    const int tid = threadIdx.x;
    const int lane = tid & 31, wid = tid >> 5;
    const int wm = wid >> 1, wn = wid & 1;
    const int g = lane >> 2, t = lane & 3;
    const size_t tA0 = (size_t)blockIdx.y * NCH;
    const size_t tB0 = (size_t)blockIdx.x * NCH;
    const uint32_t sbase = (uint32_t)__cvta_generic_to_shared(gsm);

    float acc[2][8][4];
    #pragma unroll
    for (int mt = 0; mt < 2; ++mt)
        #pragma unroll
        for (int j = 0; j < 8; ++j)
            #pragma unroll
            for (int e = 0; e < 4; ++e) acc[mt][j][e] = 0.f;

    auto prefetch = [&](int ch, int s) {
        const uint4* ga = Ap + (tA0 + ch) * 1024 + tid;
        const uint4* gb = Bp + (tB0 + ch) * 1024 + tid;
        uint32_t sA = sbase + s * 32768;
        uint32_t sB = sA + 16384;
        #pragma unroll
        for (int i = 0; i < 4; ++i)
            cp16(sA + (tid + (i << 8)) * 16, ga + (i << 8));
        #pragma unroll
        for (int i = 0; i < 4; ++i)
            cp16(sB + (tid + (i << 8)) * 16, gb + (i << 8));
    };

    prefetch(0, 0);
    asm volatile("cp.async.commit_group;");
    prefetch(1, 1);
    asm volatile("cp.async.commit_group;");

    for (int ch = 0; ch < NCH; ++ch) {
        const int s = ch % 3;
        asm volatile("cp.async.wait_group 1;");
        __syncthreads();
        if (ch + 2 < NCH) prefetch(ch + 2, (ch + 2) % 3);
        asm volatile("cp.async.commit_group;");

        const uint32_t* As = gsm + s * 8192;
        const uint32_t* Bs = As + 4096;
        #pragma unroll
        for (int ks = 0; ks < 4; ++ks) {
            uint4 af[2], bf[4];
            const int sl = lane ^ (ks << 1);
            #pragma unroll
            for (int mt = 0; mt < 2; ++mt)
                af[mt] = *reinterpret_cast<const uint4*>(
                    &As[(((wm*2 + mt)*4 + ks)*32 + sl) * 4]);
            #pragma unroll
            for (int p = 0; p < 4; ++p)
                bf[p] = *reinterpret_cast<const uint4*>(
                    &Bs[(((wn*4 + p)*4 + ks)*32 + sl) * 4]);
            #pragma unroll
            for (int mt = 0; mt < 2; ++mt)
                #pragma unroll
                for (int p = 0; p < 4; ++p) {
                    mma_tf32(acc[mt][2*p],   af[mt], bf[p].x, bf[p].y);
                    mma_tf32(acc[mt][2*p+1], af[mt], bf[p].z, bf[p].w);
                }
        }
    }

    const int bm = blockIdx.y * 128, bn = blockIdx.x * 128;
    #pragma unroll
    for (int mt = 0; mt < 2; ++mt) {
        #pragma unroll
        for (int j = 0; j < 8; ++j) {
            int m = bm + wm*32 + mt*16 + g;
            int n = bn + wn*64 + j*8 + t*2;
            *reinterpret_cast<float2*>(C + (size_t)m * Dq + n)       = make_float2(acc[mt][j][0], acc[mt][j][1]);
            *reinterpret_cast<float2*>(C + (size_t)(m + 8) * Dq + n) = make_float2(acc[mt][j][2], acc[mt][j][3]);
        }
    }
}

// ---------------------------------------------------------------------------
// Tensor-core causal flash attention (R13 machinery; Q streamed pre-packed).
// Block = 128 q-rows; 256 threads = 8 warps x m16; n=64 tiles; 2 CTAs/SM.
// Smem (u32): QA 0..8K | PA 8K..16K | KB 16K..20K | VB 20K..24K = 96KB.
// ---------------------------------------------------------------------------
extern __shared__ uint32_t sm_u[];
__global__ void __launch_bounds__(256, 2) attn_tc(const uint4* __restrict__ qp,
                                                  const uint4* __restrict__ kp,
                                                  const uint4* __restrict__ vp,
                                                  uint32_t* __restrict__ ap)
{
    uint4* QA = reinterpret_cast<uint4*>(sm_u);              // 2048 u4 (32KB)
    uint4* PA = reinterpret_cast<uint4*>(sm_u + 8192);       // 2048 u4 (32KB)
    const uint32_t sbase = (uint32_t)__cvta_generic_to_shared(sm_u);

    const int tid  = threadIdx.x;
    const int lane = tid & 31, w = tid >> 5;                 // w: 0..7
    const int g = lane >> 2, t = lane & 3;
    const int qb = 15 - blockIdx.x;                          // heavy blocks first
    const int bh = blockIdx.y;
    const int b = bh >> 4, h = bh & 15;
    const int q0 = qb * 128;

    // ---- Stream pre-packed QA tile (32KB, produced by gemm_qkv z=0) ----
    {
        const uint4* qt4 = qp + ((size_t)bh * 16 + qb) * 2048;
        uint32_t sQ = sbase;
        #pragma unroll
        for (int i = 0; i < 8; ++i)
            cp16(sQ + (tid + (i << 8)) * 16, qt4 + tid + (i << 8));
        asm volatile("cp.async.commit_group;");
    }

    const int row_hi = q0 + w*16 + 15;
    float mst0 = LNEG, mst1 = LNEG, lst0 = 0.f, lst1 = 0.f;
    float Od[8][4];
    #pragma unroll
    for (int n8 = 0; n8 < 8; ++n8)
        #pragma unroll
        for (int e = 0; e < 4; ++e) Od[n8][e] = 0.f;

    const int jmax = 2*qb + 1;
    for (int j = 0; j <= jmax; ++j) {
        const int key0 = j << 6;
        __syncthreads();                       // prior-tile smem reads done

        // KV copy into single buffer (sibling CTA hides latency)
        {
            const uint4* kpt4 = kp + ((size_t)bh * NTILES + j) * 1024;
            const uint4* vpt4 = vp + ((size_t)bh * NTILES + j) * 1024;
            uint32_t sK = sbase + 16384 * 4;
            uint32_t sV = sbase + 20480 * 4;
            #pragma unroll
            for (int i = 0; i < 4; ++i)
                cp16(sK + (tid + (i << 8)) * 16, kpt4 + tid + (i << 8));
            #pragma unroll
            for (int i = 0; i < 4; ++i)
                cp16(sV + (tid + (i << 8)) * 16, vpt4 + tid + (i << 8));
            asm volatile("cp.async.commit_group;");
            asm volatile("cp.async.wait_group 0;");   // QA + KV both done
        }
        __syncthreads();

        if (key0 <= row_hi) {
            const uint4* KB4 = reinterpret_cast<const uint4*>(sm_u + 16384);
            const uint4* VB4 = reinterpret_cast<const uint4*>(sm_u + 20480);

            float acc[8][4];
            #pragma unroll
            for (int n8 = 0; n8 < 8; ++n8)
                #pragma unroll
                for (int e = 0; e < 4; ++e) acc[n8][e] = 0.f;

            // ---- QK^T: one LDS.128 per n8-pair ----
            #pragma unroll
            for (int kk = 0; kk < 8; ++kk) {
                uint4 aq = QA[w*256 + g*32 + 4*(kk ^ g) + t];
                #pragma unroll
                for (int qp2 = 0; qp2 < 4; ++qp2) {
                    uint4 kb = KB4[(qp2*8 + g)*32 + 4*(kk ^ g) + t];
                    mma_tf32(acc[2*qp2],   aq, kb.x, kb.y);
                    mma_tf32(acc[2*qp2+1], aq, kb.z, kb.w);
                }
            }
            if (key0 + 63 > q0 + w*16) {
                int r0 = q0 + w*16 + g, r1 = r0 + 8;
                #pragma unroll
                for (int n8 = 0; n8 < 8; ++n8) {
                    int c0 = key0 + 8*n8 + 2*t, c1 = c0 + 1;
                    if (c0 > r0) acc[n8][0] = LNEG;
                    if (c1 > r0) acc[n8][1] = LNEG;
                    if (c0 > r1) acc[n8][2] = LNEG;
                    if (c1 > r1) acc[n8][3] = LNEG;
                }
            }
            float t0 = LNEG, t1 = LNEG;
            #pragma unroll
            for (int n8 = 0; n8 < 8; ++n8) {
                t0 = fmaxf(t0, fmaxf(acc[n8][0], acc[n8][1]));
                t1 = fmaxf(t1, fmaxf(acc[n8][2], acc[n8][3]));
            }
            t0 = fmaxf(t0, __shfl_xor_sync(0xffffffffu, t0, 1));
            t0 = fmaxf(t0, __shfl_xor_sync(0xffffffffu, t0, 2));
            t1 = fmaxf(t1, __shfl_xor_sync(0xffffffffu, t1, 1));
            t1 = fmaxf(t1, __shfl_xor_sync(0xffffffffu, t1, 2));
            float m0n = fmaxf(mst0, t0), m1n = fmaxf(mst1, t1);
            bool same = (m0n == mst0) && (m1n == mst1);
            bool allsame = __all_sync(0xffffffffu, same);
            float c0 = ex2(mst0 - m0n), c1 = ex2(mst1 - m1n);
            float s0 = 0.f, s1 = 0.f;

            int d0 = 2*t, d1 = 2*t + 1;
            int tw0 = d0 & 3, sl0 = (d0 >> 2) << 1;
            int tw1 = d1 & 3, sl1 = (d1 >> 2) << 1;
            #pragma unroll
            for (int n8 = 0; n8 < 8; ++n8) {
                float p00 = ex2(acc[n8][0] - m0n);
                float p01 = ex2(acc[n8][1] - m0n);
                float p10 = ex2(acc[n8][2] - m1n);
                float p11 = ex2(acc[n8][3] - m1n);
                s0 += p00 + p01;
                s1 += p10 + p11;
                uint32_t* pw = reinterpret_cast<uint32_t*>(&PA[w*256 + g*32 + 4*(n8 ^ g)]);
                pw[tw0*4 + sl0]     = f2tf(p00);
                pw[tw0*4 + sl0 + 1] = f2tf(p10);
                pw[tw1*4 + sl1]     = f2tf(p01);
                pw[tw1*4 + sl1 + 1] = f2tf(p11);
            }
            lst0 = lst0 * c0 + s0;       // c==1 exactly when max unchanged
            lst1 = lst1 * c1 + s1;
            mst0 = m0n; mst1 = m1n;
            if (!allsame) {
                #pragma unroll
                for (int n8 = 0; n8 < 8; ++n8) {
                    Od[n8][0] *= c0; Od[n8][1] *= c0;
                    Od[n8][2] *= c1; Od[n8][3] *= c1;
                }
            }
            __syncwarp();

            // ---- P @ V: one LDS.128 per n8-pair ----
            #pragma unroll
            for (int kk = 0; kk < 8; ++kk) {
                uint4 pa = PA[w*256 + g*32 + 4*(kk ^ g) + t];
                #pragma unroll
                for (int qp2 = 0; qp2 < 4; ++qp2) {
                    uint4 vb = VB4[(qp2*8 + g)*32 + 4*(kk ^ g) + t];
                    mma_tf32(Od[2*qp2],   pa, vb.x, vb.y);
                    mma_tf32(Od[2*qp2+1], pa, vb.z, vb.w);
                }
            }
        }
    }

    // ---- epilogue: normalize, stage packed-A layout (2 tiles), copy out ----
    lst0 += __shfl_xor_sync(0xffffffffu, lst0, 1);
    lst0 += __shfl_xor_sync(0xffffffffu, lst0, 2);
    lst1 += __shfl_xor_sync(0xffffffffu, lst1, 1);
    lst1 += __shfl_xor_sync(0xffffffffu, lst1, 2);
    float i0 = 1.f / lst0, i1 = 1.f / lst1;
    __syncthreads();                     // all tiles done; QA region reusable

    #pragma unroll
    for (int n8 = 0; n8 < 8; ++n8)
        #pragma unroll
        for (int e = 0; e < 4; ++e) {
            float val = Od[n8][e] * ((e >> 1) ? i1 : i0);
            int r = w*16 + g + ((e >> 1) << 3);           // 0..127
            int col_loc = 8*n8 + 2*t + (e & 1);           // 0..63
            int chh = col_loc >> 5, c = col_loc & 31;
            int mt = r >> 4, rr = r & 15;
            int ks = c >> 3, hi = (c >> 2) & 1, jw = c & 3;
            int idx = ((mt*4 + ks)*32 + ((((rr & 7) << 2) | jw) ^ (ks << 1)))*4 + (rr >> 3) + 2*hi;
            sm_u[chh*4096 + idx] = f2tf(val);
        }
    __syncthreads();

    {
        int rb = b*16 + qb;
        #pragma unroll
        for (int chh = 0; chh < 2; ++chh) {
            int ch = h*2 + chh;
            uint4* dst = reinterpret_cast<uint4*>(ap) + ((size_t)rb * NCH + ch) * 1024;
            const uint4* src = reinterpret_cast<const uint4*>(sm_u) + chh * 1024;
            #pragma unroll
            for (int i = 0; i < 4; ++i)
                dst[tid + (i << 8)] = src[tid + (i << 8)];
        }
    }
}

// ---------------------------------------------------------------------------
extern "C" void kernel_launch(void* const* d_in, const int* in_sizes, int n_in,
                              void* d_out, int out_size)
{
    const float* x  = (const float*)d_in[0];
    const float* wq = (const float*)d_in[1];
    const float* wk = (const float*)d_in[2];
    const float* wv = (const float*)d_in[3];
    const float* wo = (const float*)d_in[4];
    float* out = (float*)d_out;

    uint4 *qpp, *kpp, *vpp, *xp, *ap, *pwq, *pwk, *pwv, *pwo;
    cudaGetSymbolAddress((void**)&qpp, g_qp);
    cudaGetSymbolAddress((void**)&kpp, g_kp);
    cudaGetSymbolAddress((void**)&vpp, g_vp);
    cudaGetSymbolAddress((void**)&xp,  g_xp);
    cudaGetSymbolAddress((void**)&ap,  g_ap);
    cudaGetSymbolAddress((void**)&pwq, g_wq);
    cudaGetSymbolAddress((void**)&pwk, g_wk);
    cudaGetSymbolAddress((void**)&pwv, g_wv);
    cudaGetSymbolAddress((void**)&pwo, g_wo);

    pack_a<<<dim3(Mrows/128, NCH), 256>>>(x, (uint32_t*)xp);
    pack_w<<<dim3(8, NCH, 4), 256>>>(wq, wk, wv, wo,
                                     (uint32_t*)pwq, (uint32_t*)pwk,
                                     (uint32_t*)pwv, (uint32_t*)pwo);

    int smem_gemm = 98304;
    cudaFuncSetAttribute(gemm_qkv,    cudaFuncAttributeMaxDynamicSharedMemorySize, smem_gemm);
    cudaFuncSetAttribute(gemm_packed, cudaFuncAttributeMaxDynamicSharedMemorySize, smem_gemm);

    gemm_qkv<<<dim3(8, 64, 3), 256, smem_gemm>>>(xp, pwq, pwk, pwv,
                                                 (uint32_t*)qpp,
                                                 (uint32_t*)kpp, (uint32_t*)vpp);

    int smem_attn = 98304;   // 96KB -> 2 CTAs/SM
    cudaFuncSetAttribute(attn_tc, cudaFuncAttributeMaxDynamicSharedMemorySize, smem_attn);
    attn_tc<<<dim3(16, 64), 256, smem_attn>>>(qpp, kpp, vpp, (uint32_t*)ap);

    gemm_packed<<<dim3(8, 64), 256, smem_gemm>>>(ap, pwo, out);
}

// round 15
// speedup vs baseline: 1.0164x; 1.0164x over previous
#include <cuda_runtime.h>
#include <cstdint>
#include <cstddef>

#define Bq 4
#define Sq 2048
#define Dq 1024
#define Hq 16
#define DKq 64
#define Mrows (Bq*Sq)
#define NTILES 32          // key tiles per (b,h)
#define NCH 32             // K chunks per GEMM (K=1024 / 32)
#define LNEG -1e30f

// Scratch (allocation-free rule: __device__ globals)
__device__ uint4 g_qp[(size_t)64*16*2048];         // packed Q tiles (QA layout)
__device__ uint4 g_kp[(size_t)64*NTILES*1024];     // packed K fragments (paired n8)
__device__ uint4 g_vp[(size_t)64*NTILES*1024];     // packed V fragments (paired n8)
__device__ uint4 g_xp[(size_t)Mrows*Dq/4];          // packed x   (A layout)
__device__ uint4 g_ap[(size_t)Mrows*Dq/4];          // packed attn out (A layout)
__device__ uint4 g_wq[(size_t)Dq*Dq/4];             // packed weights (B layout)
__device__ uint4 g_wk[(size_t)Dq*Dq/4];
__device__ uint4 g_wv[(size_t)Dq*Dq/4];
__device__ uint4 g_wo[(size_t)Dq*Dq/4];

__device__ __forceinline__ uint32_t f2tf(float f) {
    uint32_t u;
    asm("cvt.rna.tf32.f32 %0, %1;" : "=r"(u) : "f"(f));
    return u;
}
__device__ __forceinline__ float ex2(float x) {
    float r;
    asm("ex2.approx.f32 %0, %1;" : "=f"(r) : "f"(x));
    return r;
}
__device__ __forceinline__ void mma_tf32(float* c, uint4 a, uint32_t b0, uint32_t b1) {
    asm volatile("mma.sync.aligned.m16n8k8.row.col.f32.tf32.tf32.f32 "
        "{%0,%1,%2,%3}, {%4,%5,%6,%7}, {%8,%9}, {%0,%1,%2,%3};"
        : "+f"(c[0]), "+f"(c[1]), "+f"(c[2]), "+f"(c[3])
        : "r"(a.x), "r"(a.y), "r"(a.z), "r"(a.w), "r"(b0), "r"(b1));
}
__device__ __forceinline__ void cp16(uint32_t sa, const void* g) {
    asm volatile("cp.async.cg.shared.global [%0], [%1], 16;" :: "r"(sa), "l"(g));
}

// ---------------------------------------------------------------------------
// Pack a float matrix [R x 1024] into A-layout fragment tiles (TF32).
// ---------------------------------------------------------------------------
__global__ void __launch_bounds__(256) pack_a(const float* __restrict__ A,
                                              uint32_t* __restrict__ out)
{
    const int rb = blockIdx.x, ch = blockIdx.y, tid = threadIdx.x;
    const int rbase = tid >> 3, kc = (tid & 7) << 2;
    const int ks = (tid & 7) >> 1, hi = tid & 1;
    uint32_t* ot = out + ((size_t)rb * NCH + ch) * 4096;
    const float* Ab = A + ((size_t)rb * 128) * Dq + ch * 32;
    #pragma unroll
    for (int i = 0; i < 4; ++i) {
        int r = rbase + 32*i;
        float4 f4 = *reinterpret_cast<const float4*>(Ab + (size_t)r * Dq + kc);
        const float* f = &f4.x;
        int mt = r >> 4, rr = r & 15;
        int w = (rr >> 3) + (hi << 1);
        int base = (mt*4 + ks) * 32;
        int l0 = (rr & 7) << 2;
        #pragma unroll
        for (int j = 0; j < 4; ++j)
            ot[(base + ((l0 + j) ^ (ks << 1))) * 4 + w] = f2tf(f[j]);
    }
}

// ---------------------------------------------------------------------------
// Pack the 4 weight matrices into B-layout fragment tiles.
// ---------------------------------------------------------------------------
__global__ void __launch_bounds__(256) pack_w(const float* __restrict__ w0,
                                              const float* __restrict__ w1,
                                              const float* __restrict__ w2,
                                              const float* __restrict__ w3,
                                              uint32_t* __restrict__ o0,
                                              uint32_t* __restrict__ o1,
                                              uint32_t* __restrict__ o2,
                                              uint32_t* __restrict__ o3)
{
    const float* W = (blockIdx.z == 0) ? w0 : (blockIdx.z == 1) ? w1
                    : (blockIdx.z == 2) ? w2 : w3;
    uint32_t* O = (blockIdx.z == 0) ? o0 : (blockIdx.z == 1) ? o1
                 : (blockIdx.z == 2) ? o2 : o3;
    const int nb = blockIdx.x, ch = blockIdx.y, tid = threadIdx.x;
    const int rbase = tid >> 3, kc = (tid & 7) << 2;
    const int ks = (tid & 7) >> 1, hi = tid & 1;
    uint32_t* ot = O + ((size_t)nb * NCH + ch) * 4096;
    const float* Wb = W + ((size_t)nb * 128) * Dq + ch * 32;
    #pragma unroll
    for (int i = 0; i < 4; ++i) {
        int n = rbase + 32*i;
        float4 f4 = *reinterpret_cast<const float4*>(Wb + (size_t)n * Dq + kc);
        const float* f = &f4.x;
        int nt = n >> 3, gg = n & 7;
        int w = ((nt & 1) << 1) + hi;
        int base = ((nt >> 1)*4 + ks) * 32;
        int l0 = gg << 2;
        #pragma unroll
        for (int j = 0; j < 4; ++j)
            ot[(base + ((l0 + j) ^ (ks << 1))) * 4 + w] = f2tf(f[j]);
    }
}

// ---------------------------------------------------------------------------
// Fused QKV TF32 GEMM on pre-packed operands. grid (8, 64, 3).
// z=0 -> Q in attn QA fragment layout (scaled by 0.125*log2e);
// z=1 -> paired kp; z=2 -> paired vp.
// ---------------------------------------------------------------------------
extern __shared__ uint32_t gsm[];
__global__ void __launch_bounds__(256, 2) gemm_qkv(const uint4* __restrict__ Ap,
                                                   const uint4* __restrict__ Bq_,
                                                   const uint4* __restrict__ Bk_,
                                                   const uint4* __restrict__ Bv_,
                                                   uint32_t* __restrict__ qp32,
                                                   uint32_t* __restrict__ kp32,
                                                   uint32_t* __restrict__ vp32)
{
    const int tid = threadIdx.x;
    const int lane = tid & 31, wid = tid >> 5;
    const int wm = wid >> 1, wn = wid & 1;
    const int g = lane >> 2, t = lane & 3;
    const int z = blockIdx.z;
    const uint4* Bp = (z == 0) ? Bq_ : (z == 1) ? Bk_ : Bv_;
    const size_t tA0 = (size_t)blockIdx.y * NCH;
    const size_t tB0 = (size_t)blockIdx.x * NCH;
    const uint32_t sbase = (uint32_t)__cvta_generic_to_shared(gsm);

    float acc[2][8][4];
    #pragma unroll
    for (int mt = 0; mt < 2; ++mt)
        #pragma unroll
        for (int j = 0; j < 8; ++j)
            #pragma unroll
            for (int e = 0; e < 4; ++e) acc[mt][j][e] = 0.f;

    auto prefetch = [&](int ch, int s) {
        const uint4* ga = Ap + (tA0 + ch) * 1024 + tid;
        const uint4* gb = Bp + (tB0 + ch) * 1024 + tid;
        uint32_t sA = sbase + s * 32768;
        uint32_t sB = sA + 16384;
        #pragma unroll
        for (int i = 0; i < 4; ++i)
            cp16(sA + (tid + (i << 8)) * 16, ga + (i << 8));
        #pragma unroll
        for (int i = 0; i < 4; ++i)
            cp16(sB + (tid + (i << 8)) * 16, gb + (i << 8));
    };

    prefetch(0, 0);
    asm volatile("cp.async.commit_group;");
    prefetch(1, 1);
    asm volatile("cp.async.commit_group;");

    for (int ch = 0; ch < NCH; ++ch) {
        const int s = ch % 3;
        asm volatile("cp.async.wait_group 1;");
        __syncthreads();
        if (ch + 2 < NCH) prefetch(ch + 2, (ch + 2) % 3);
        asm volatile("cp.async.commit_group;");

        const uint32_t* As = gsm + s * 8192;
        const uint32_t* Bs = As + 4096;
        #pragma unroll
        for (int ks = 0; ks < 4; ++ks) {
            uint4 af[2], bf[4];
            const int sl = lane ^ (ks << 1);
            #pragma unroll
            for (int mt = 0; mt < 2; ++mt)
                af[mt] = *reinterpret_cast<const uint4*>(
                    &As[(((wm*2 + mt)*4 + ks)*32 + sl) * 4]);
            #pragma unroll
            for (int p = 0; p < 4; ++p)
                bf[p] = *reinterpret_cast<const uint4*>(
                    &Bs[(((wn*4 + p)*4 + ks)*32 + sl) * 4]);
            #pragma unroll
            for (int mt = 0; mt < 2; ++mt)
                #pragma unroll
                for (int p = 0; p < 4; ++p) {
                    mma_tf32(acc[mt][2*p],   af[mt], bf[p].x, bf[p].y);
                    mma_tf32(acc[mt][2*p+1], af[mt], bf[p].z, bf[p].w);
                }
        }
    }

    const int bm = blockIdx.y * 128, bn = blockIdx.x * 128;

    // All epilogues stage via smem; pipeline is dead after this point.
    asm volatile("cp.async.wait_group 0;");
    __syncthreads();

    if (z == 0) {
        // Q: stage attn QA fragment layout (scaled), 2 head-quadrants x 32KB
        const float qsc = 0.125f * 1.44269504f;
        #pragma unroll
        for (int mt = 0; mt < 2; ++mt)
            #pragma unroll
            for (int j = 0; j < 8; ++j)
                #pragma unroll
                for (int e = 0; e < 4; ++e) {
                    int rloc = wm*32 + mt*16 + g + ((e >> 1) << 3);   // 0..127
                    int nloc = wn*64 + j*8 + 2*t + (e & 1);           // 0..127
                    int ch2 = nloc >> 6, dkl = nloc & 63;
                    int sl = rloc >> 4, ri = rloc & 15;
                    int gg = ri & 7, half = ri >> 3;
                    int kk = dkl >> 3, cc = dkl & 7;
                    int tt = cc & 3, hi4 = cc >> 2;
                    int idx = (sl*256 + gg*32 + 4*(kk ^ gg) + tt)*4 + half + 2*hi4;
                    gsm[ch2*8192 + idx] = f2tf(acc[mt][j][e] * qsc);
                }
        __syncthreads();
        const int b = bm >> 11, qt = (bm & 2047) >> 7, h0 = bn >> 6;
        #pragma unroll
        for (int ch2 = 0; ch2 < 2; ++ch2) {
            int bh = b*16 + h0 + ch2;
            uint4* dst = reinterpret_cast<uint4*>(qp32) + ((size_t)bh*16 + qt) * 2048;
            const uint4* src = reinterpret_cast<const uint4*>(gsm) + ch2 * 2048;
            #pragma unroll
            for (int i = 0; i < 8; ++i)
                dst[tid + (i << 8)] = src[tid + (i << 8)];
        }
        return;
    }

    // K/V: stage paired-fragment layout into smem, then coalesced copy
    #pragma unroll
    for (int mt = 0; mt < 2; ++mt)
        #pragma unroll
        for (int j = 0; j < 8; ++j)
            #pragma unroll
            for (int e = 0; e < 4; ++e) {
                int rloc = wm*32 + mt*16 + g + ((e >> 1) << 3);   // 0..127
                int nloc = wn*64 + j*8 + 2*t + (e & 1);           // 0..127
                int rh = rloc >> 6, ch2 = nloc >> 6;
                int keyl = rloc & 63, dkl = nloc & 63;
                int idx;
                if (z == 1) {
                    int gq = keyl & 7, n8k = keyl >> 3;
                    int qk = n8k >> 1, half = n8k & 1;
                    int kk2 = dkl >> 3, dc = dkl & 7;
                    idx = ((qk*8 + gq)*32 + 4*(kk2 ^ gq) + (dc & 3))*4 + half*2 + (dc >> 2);
                } else {
                    int gq = dkl & 7, n8v = dkl >> 3;
                    int qv = n8v >> 1, half = n8v & 1;
                    int kk3 = keyl >> 3, kc2 = keyl & 7;
                    idx = ((qv*8 + gq)*32 + 4*(kk3 ^ gq) + (kc2 & 3))*4 + half*2 + (kc2 >> 2);
                }
                gsm[(rh*2 + ch2)*4096 + idx] = f2tf(acc[mt][j][e]);
            }
    __syncthreads();

    uint32_t* dstb = (z == 1) ? kp32 : vp32;
    const int b = bm >> 11, jt0 = (bm & 2047) >> 6, h0 = bn >> 6;
    #pragma unroll
    for (int qd = 0; qd < 4; ++qd) {
        int rh = qd >> 1, ch2 = qd & 1;
        int bh = b*16 + h0 + ch2;
        int jt = jt0 + rh;
        uint4* dst = reinterpret_cast<uint4*>(dstb) + ((size_t)bh*NTILES + jt) * 1024;
        const uint4* src = reinterpret_cast<const uint4*>(gsm) + qd * 1024;
        #pragma unroll
        for (int i = 0; i < 4; ++i)
            dst[tid + (i << 8)] = src[tid + (i << 8)];
    }
}

// ---------------------------------------------------------------------------
// TF32 GEMM on pre-packed operands (final O-projection), float epilogue.
// ---------------------------------------------------------------------------
__global__ void __launch_bounds__(256, 2) gemm_packed(const uint4* __restrict__ Ap,
                                                      const uint4* __restrict__ Bp,
                                                      float* __restrict__ C)
{
    const int tid = threadIdx.x;
    const int lane = tid & 31, wid = tid >> 5;
    const int wm = wid >> 1, wn = wid & 1;
    const int g = lane >> 2, t = lane & 3;
    const size_t tA0 = (size_t)blockIdx.y * NCH;
    const size_t tB0 = (size_t)blockIdx.x * NCH;
    const uint32_t sbase = (uint32_t)__cvta_generic_to_shared(gsm);

    float acc[2][8][4];
    #pragma unroll
    for (int mt = 0; mt < 2; ++mt)
        #pragma unroll
        for (int j = 0; j < 8; ++j)
            #pragma unroll
            for (int e = 0; e < 4; ++e) acc[mt][j][e] = 0.f;

    auto prefetch = [&](int ch, int s) {
        const uint4* ga = Ap + (tA0 + ch) * 1024 + tid;
        const uint4* gb = Bp + (tB0 + ch) * 1024 + tid;
        uint32_t sA = sbase + s * 32768;
        uint32_t sB = sA + 16384;
        #pragma unroll
        for (int i = 0; i < 4; ++i)
            cp16(sA + (tid + (i << 8)) * 16, ga + (i << 8));
        #pragma unroll
        for (int i = 0; i < 4; ++i)
            cp16(sB + (tid + (i << 8)) * 16, gb + (i << 8));
    };

    prefetch(0, 0);
    asm volatile("cp.async.commit_group;");
    prefetch(1, 1);
    asm volatile("cp.async.commit_group;");

    for (int ch = 0; ch < NCH; ++ch) {
        const int s = ch % 3;
        asm volatile("cp.async.wait_group 1;");
        __syncthreads();
        if (ch + 2 < NCH) prefetch(ch + 2, (ch + 2) % 3);
        asm volatile("cp.async.commit_group;");

        const uint32_t* As = gsm + s * 8192;
        const uint32_t* Bs = As + 4096;
        #pragma unroll
        for (int ks = 0; ks < 4; ++ks) {
            uint4 af[2], bf[4];
            const int sl = lane ^ (ks << 1);
            #pragma unroll
            for (int mt = 0; mt < 2; ++mt)
                af[mt] = *reinterpret_cast<const uint4*>(
                    &As[(((wm*2 + mt)*4 + ks)*32 + sl) * 4]);
            #pragma unroll
            for (int p = 0; p < 4; ++p)
                bf[p] = *reinterpret_cast<const uint4*>(
                    &Bs[(((wn*4 + p)*4 + ks)*32 + sl) * 4]);
            #pragma unroll
            for (int mt = 0; mt < 2; ++mt)
                #pragma unroll
                for (int p = 0; p < 4; ++p) {
                    mma_tf32(acc[mt][2*p],   af[mt], bf[p].x, bf[p].y);
                    mma_tf32(acc[mt][2*p+1], af[mt], bf[p].z, bf[p].w);
                }
        }
    }

    const int bm = blockIdx.y * 128, bn = blockIdx.x * 128;
    #pragma unroll
    for (int mt = 0; mt < 2; ++mt) {
        #pragma unroll
        for (int j = 0; j < 8; ++j) {
            int m = bm + wm*32 + mt*16 + g;
            int n = bn + wn*64 + j*8 + t*2;
            *reinterpret_cast<float2*>(C + (size_t)m * Dq + n)       = make_float2(acc[mt][j][0], acc[mt][j][1]);
            *reinterpret_cast<float2*>(C + (size_t)(m + 8) * Dq + n) = make_float2(acc[mt][j][2], acc[mt][j][3]);
        }
    }
}

// ---------------------------------------------------------------------------
// Tensor-core causal flash attention.
// Block = 128 q-rows; 256 threads = 8 warps x m16; n=64 tiles; 2 CTAs/SM.
// Q fragments live in REGISTERS (loaded once from pre-packed tile) -> QA smem
// freed -> KV double-buffered; copy of tile j+1 overlaps compute of tile j.
// Smem (u32): PA 0..8K | stage s at 8K+s*8K (KB 4K, VB 4K) = 96KB.
// ---------------------------------------------------------------------------
extern __shared__ uint32_t sm_u[];
__global__ void __launch_bounds__(256, 2) attn_tc(const uint4* __restrict__ qp,
                                                  const uint4* __restrict__ kp,
                                                  const uint4* __restrict__ vp,
                                                  uint32_t* __restrict__ ap)
{
    uint4* PA = reinterpret_cast<uint4*>(sm_u);              // 2048 u4 (32KB)
    const uint32_t sbase = (uint32_t)__cvta_generic_to_shared(sm_u);

    const int tid  = threadIdx.x;
    const int lane = tid & 31, w = tid >> 5;                 // w: 0..7
    const int g = lane >> 2, t = lane & 3;
    const int qb = 15 - blockIdx.x;                          // heavy blocks first
    const int bh = blockIdx.y;
    const int b = bh >> 4, h = bh & 15;
    const int q0 = qb * 128;

    // ---- Load Q fragments into registers (pre-packed by gemm_qkv z=0) ----
    uint4 qreg[8];
    {
        const uint4* qt4 = qp + ((size_t)bh * 16 + qb) * 2048 + w * 256;
        #pragma unroll
        for (int kk = 0; kk < 8; ++kk)
            qreg[kk] = qt4[g*32 + 4*(kk ^ g) + t];
    }

    auto prefetch = [&](int j, int s) {
        const uint4* kpt4 = kp + ((size_t)bh * NTILES + j) * 1024;
        const uint4* vpt4 = vp + ((size_t)bh * NTILES + j) * 1024;
        uint32_t sK = sbase + (8192 + s * 8192) * 4;
        uint32_t sV = sK + 4096 * 4;
        #pragma unroll
        for (int i = 0; i < 4; ++i)
            cp16(sK + (tid + (i << 8)) * 16, kpt4 + tid + (i << 8));
        #pragma unroll
        for (int i = 0; i < 4; ++i)
            cp16(sV + (tid + (i << 8)) * 16, vpt4 + tid + (i << 8));
    };

    const int row_hi = q0 + w*16 + 15;
    float mst0 = LNEG, mst1 = LNEG, lst0 = 0.f, lst1 = 0.f;
    float Od[8][4];
    #pragma unroll
    for (int n8 = 0; n8 < 8; ++n8)
        #pragma unroll
        for (int e = 0; e < 4; ++e) Od[n8][e] = 0.f;

    const int jmax = 2*qb + 1;
    prefetch(0, 0);
    asm volatile("cp.async.commit_group;");

    for (int j = 0; j <= jmax; ++j) {
        const int s = j & 1;
        const int key0 = j << 6;
        if (j + 1 <= jmax) prefetch(j + 1, s ^ 1);  // s^1 free (synced last iter)
        asm volatile("cp.async.commit_group;");
        asm volatile("cp.async.wait_group 1;");     // tile j arrived (this thread)
        __syncthreads();                             // ... and all other threads'

        if (key0 <= row_hi) {
            const uint4* KB4 = reinterpret_cast<const uint4*>(sm_u + 8192 + s * 8192);
            const uint4* VB4 = KB4 + 1024;

            float acc[8][4];
            #pragma unroll
            for (int n8 = 0; n8 < 8; ++n8)
                #pragma unroll
                for (int e = 0; e < 4; ++e) acc[n8][e] = 0.f;

            // ---- QK^T: Q from registers, one LDS.128 per n8-pair ----
            #pragma unroll
            for (int kk = 0; kk < 8; ++kk) {
                #pragma unroll
                for (int qp2 = 0; qp2 < 4; ++qp2) {
                    uint4 kb = KB4[(qp2*8 + g)*32 + 4*(kk ^ g) + t];
                    mma_tf32(acc[2*qp2],   qreg[kk], kb.x, kb.y);
                    mma_tf32(acc[2*qp2+1], qreg[kk], kb.z, kb.w);
                }
            }
            if (key0 + 63 > q0 + w*16) {
                int r0 = q0 + w*16 + g, r1 = r0 + 8;
                #pragma unroll
                for (int n8 = 0; n8 < 8; ++n8) {
                    int c0 = key0 + 8*n8 + 2*t, c1 = c0 + 1;
                    if (c0 > r0) acc[n8][0] = LNEG;
                    if (c1 > r0) acc[n8][1] = LNEG;
                    if (c0 > r1) acc[n8][2] = LNEG;
                    if (c1 > r1) acc[n8][3] = LNEG;
                }
            }
            float t0 = LNEG, t1 = LNEG;
            #pragma unroll
            for (int n8 = 0; n8 < 8; ++n8) {
                t0 = fmaxf(t0, fmaxf(acc[n8][0], acc[n8][1]));
                t1 = fmaxf(t1, fmaxf(acc[n8][2], acc[n8][3]));
            }
            t0 = fmaxf(t0, __shfl_xor_sync(0xffffffffu, t0, 1));
            t0 = fmaxf(t0, __shfl_xor_sync(0xffffffffu, t0, 2));
            t1 = fmaxf(t1, __shfl_xor_sync(0xffffffffu, t1, 1));
            t1 = fmaxf(t1, __shfl_xor_sync(0xffffffffu, t1, 2));
            float m0n = fmaxf(mst0, t0), m1n = fmaxf(mst1, t1);
            bool same = (m0n == mst0) && (m1n == mst1);
            bool allsame = __all_sync(0xffffffffu, same);
            float c0 = ex2(mst0 - m0n), c1 = ex2(mst1 - m1n);
            float s0 = 0.f, s1 = 0.f;

            int d0 = 2*t, d1 = 2*t + 1;
            int tw0 = d0 & 3, sl0 = (d0 >> 2) << 1;
            int tw1 = d1 & 3, sl1 = (d1 >> 2) << 1;
            #pragma unroll
            for (int n8 = 0; n8 < 8; ++n8) {
                float p00 = ex2(acc[n8][0] - m0n);
                float p01 = ex2(acc[n8][1] - m0n);
                float p10 = ex2(acc[n8][2] - m1n);
                float p11 = ex2(acc[n8][3] - m1n);
                s0 += p00 + p01;
                s1 += p10 + p11;
                uint32_t* pw = reinterpret_cast<uint32_t*>(&PA[w*256 + g*32 + 4*(n8 ^ g)]);
                pw[tw0*4 + sl0]     = f2tf(p00);
                pw[tw0*4 + sl0 + 1] = f2tf(p10);
                pw[tw1*4 + sl1]     = f2tf(p01);
                pw[tw1*4 + sl1 + 1] = f2tf(p11);
            }
            lst0 = lst0 * c0 + s0;       // c==1 exactly when max unchanged
            lst1 = lst1 * c1 + s1;
            mst0 = m0n; mst1 = m1n;
            if (!allsame) {
                #pragma unroll
                for (int n8 = 0; n8 < 8; ++n8) {
                    Od[n8][0] *= c0; Od[n8][1] *= c0;
                    Od[n8][2] *= c1; Od[n8][3] *= c1;
                }
            }
            __syncwarp();

            // ---- P @ V: one LDS.128 per n8-pair ----
            #pragma unroll
            for (int kk = 0; kk < 8; ++kk) {
                uint4 pa = PA[w*256 + g*32 + 4*(kk ^ g) + t];
                #pragma unroll
                for (int qp2 = 0; qp2 < 4; ++qp2) {
                    uint4 vb = VB4[(qp2*8 + g)*32 + 4*(kk ^ g) + t];
                    mma_tf32(Od[2*qp2],   pa, vb.x, vb.y);
                    mma_tf32(Od[2*qp2+1], pa, vb.z, vb.w);
                }
            }
        }
        __syncthreads();                 // stage s free for prefetch at j+1
    }

    // ---- epilogue: normalize, stage packed-A layout (2 tiles), copy out ----
    lst0 += __shfl_xor_sync(0xffffffffu, lst0, 1);
    lst0 += __shfl_xor_sync(0xffffffffu, lst0, 2);
    lst1 += __shfl_xor_sync(0xffffffffu, lst1, 1);
    lst1 += __shfl_xor_sync(0xffffffffu, lst1, 2);
    float i0 = 1.f / lst0, i1 = 1.f / lst1;

    #pragma unroll
    for (int n8 = 0; n8 < 8; ++n8)
        #pragma unroll
        for (int e = 0; e < 4; ++e) {
            float val = Od[n8][e] * ((e >> 1) ? i1 : i0);
            int r = w*16 + g + ((e >> 1) << 3);           // 0..127
            int col_loc = 8*n8 + 2*t + (e & 1);           // 0..63
            int chh = col_loc >> 5, c = col_loc & 31;
            int mt = r >> 4, rr = r & 15;
            int ks = c >> 3, hi = (c >> 2) & 1, jw = c & 3;
            int idx = ((mt*4 + ks)*32 + ((((rr & 7) << 2) | jw) ^ (ks << 1)))*4 + (rr >> 3) + 2*hi;
            sm_u[chh*4096 + idx] = f2tf(val);             // reuse PA region
        }
    __syncthreads();

    {
        int rb = b*16 + qb;
        #pragma unroll
        for (int chh = 0; chh < 2; ++chh) {
            int ch = h*2 + chh;
            uint4* dst = reinterpret_cast<uint4*>(ap) + ((size_t)rb * NCH + ch) * 1024;
            const uint4* src = reinterpret_cast<const uint4*>(sm_u) + chh * 1024;
            #pragma unroll
            for (int i = 0; i < 4; ++i)
                dst[tid + (i << 8)] = src[tid + (i << 8)];
        }
    }
}

// ---------------------------------------------------------------------------
extern "C" void kernel_launch(void* const* d_in, const int* in_sizes, int n_in,
                              void* d_out, int out_size)
{
    const float* x  = (const float*)d_in[0];
    const float* wq = (const float*)d_in[1];
    const float* wk = (const float*)d_in[2];
    const float* wv = (const float*)d_in[3];
    const float* wo = (const float*)d_in[4];
    float* out = (float*)d_out;

    uint4 *qpp, *kpp, *vpp, *xp, *ap, *pwq, *pwk, *pwv, *pwo;
    cudaGetSymbolAddress((void**)&qpp, g_qp);
    cudaGetSymbolAddress((void**)&kpp, g_kp);
    cudaGetSymbolAddress((void**)&vpp, g_vp);
    cudaGetSymbolAddress((void**)&xp,  g_xp);
    cudaGetSymbolAddress((void**)&ap,  g_ap);
    cudaGetSymbolAddress((void**)&pwq, g_wq);
    cudaGetSymbolAddress((void**)&pwk, g_wk);
    cudaGetSymbolAddress((void**)&pwv, g_wv);
    cudaGetSymbolAddress((void**)&pwo, g_wo);

    pack_a<<<dim3(Mrows/128, NCH), 256>>>(x, (uint32_t*)xp);
    pack_w<<<dim3(8, NCH, 4), 256>>>(wq, wk, wv, wo,
                                     (uint32_t*)pwq, (uint32_t*)pwk,
                                     (uint32_t*)pwv, (uint32_t*)pwo);

    int smem_gemm = 98304;
    cudaFuncSetAttribute(gemm_qkv,    cudaFuncAttributeMaxDynamicSharedMemorySize, smem_gemm);
    cudaFuncSetAttribute(gemm_packed, cudaFuncAttributeMaxDynamicSharedMemorySize, smem_gemm);

    gemm_qkv<<<dim3(8, 64, 3), 256, smem_gemm>>>(xp, pwq, pwk, pwv,
                                                 (uint32_t*)qpp,
                                                 (uint32_t*)kpp, (uint32_t*)vpp);

    int smem_attn = 98304;   // 96KB: PA 32 | KV 2x32 -> 2 CTAs/SM
    cudaFuncSetAttribute(attn_tc, cudaFuncAttributeMaxDynamicSharedMemorySize, smem_attn);
    attn_tc<<<dim3(16, 64), 256, smem_attn>>>(qpp, kpp, vpp, (uint32_t*)ap);

    gemm_packed<<<dim3(8, 64), 256, smem_gemm>>>(ap, pwo, out);
}